// round 16
// baseline (speedup 1.0000x reference)
#include <cuda_runtime.h>
#include <cstdint>

// Problem constants
#define BATCH    16
#define HW       (1024 * 1024)
#define HW8      (HW / 8)          // 131072 float8 per image
#define GRIDX    37                // 37*16 = 592 = 148 SMs * 4 CTAs -> one wave
#define NT       256
#define NQ       8                 // g, tg, lg, om, to, t, bn, bt
#define SMOOTH   1e-6f

#define CHUNK8   (14 * NT)         // 3584 float8 contiguous per CTA (CTAs 0..35)
// CTA 36: 131072 - 36*3584 = 2048 float8 = 8 stages. Stage = NT float8 = 8KB.

__device__ float        g_part[BATCH * GRIDX * NQ];
__device__ float        g_img[BATCH * 4];     // per-image reduced stats
__device__ unsigned int g_cnt_img[BATCH];     // zero-init; self-reset by 37th CTA
__device__ unsigned int g_count;              // zero-init; self-reset by finisher

// ---------- 256-bit streaming load, L1 bypass (sm_100+) ----------
struct f8 { float a, b, c, d, e, f, g, h; };
__device__ __forceinline__ f8 ld256(const float* p) {
    f8 r;
    asm volatile("ld.global.nc.L1::no_allocate.v8.f32 {%0,%1,%2,%3,%4,%5,%6,%7}, [%8];"
                 : "=f"(r.a), "=f"(r.b), "=f"(r.c), "=f"(r.d),
                   "=f"(r.e), "=f"(r.f), "=f"(r.g), "=f"(r.h)
                 : "l"(p));
    return r;
}

// ---------- scalar MUFU helpers ----------
__device__ __forceinline__ float tanha(float x) {
    float r; asm("tanh.approx.f32 %0, %1;" : "=f"(r) : "f"(x)); return r;
}
__device__ __forceinline__ float lg2a(float x) {
    float r; asm("lg2.approx.f32 %0, %1;" : "=f"(r) : "f"(x)); return r;
}
__device__ __forceinline__ float setgt0(float x) {
    float r; asm("set.gt.f32.f32 %0, %1, 0f00000000;" : "=f"(r) : "f"(x)); return r;
}

struct Accs { float g, tg, lg, om, to, t, bn, bt; };

// Per-element, t in {0,1}:
//   h = tanh((t-0.5)x) ; p_t = 0.5+0.5h ; l = lg2(p_t)  (ce = -ln2*l)
//   omp = 1-p_t = 0.5-0.5h ; focal elem = (0.75-0.5t)*(-ln2)*l*omp^2
//   Sp = om + t - 2*to ; Spt = t - to     (recovered at image level)
__device__ __forceinline__ void elem(Accs& A, float x, float t) {
    float z   = (t - 0.5f) * x;
    float h   = tanha(z);
    float pt  = fmaf(h, 0.5f, 0.5f);
    float l   = lg2a(pt);
    float omp = fmaf(h, -0.5f, 0.5f);
    float gg  = l * omp * omp;
    A.g  += gg;
    A.tg  = fmaf(t, gg, A.tg);
    A.lg += l;
    A.om += omp;
    A.to  = fmaf(t, omp, A.to);
    A.t  += t;
    float b = setgt0(x);
    A.bn += b;
    A.bt  = fmaf(t, b, A.bt);
}

__device__ __forceinline__ void octet(Accs& A, const f8& p, const f8& g) {
    elem(A, p.a, g.a); elem(A, p.b, g.b);
    elem(A, p.c, g.c); elem(A, p.d, g.d);
    elem(A, p.e, g.e); elem(A, p.f, g.f);
    elem(A, p.g, g.g); elem(A, p.h, g.h);
}

__device__ __forceinline__ float warp_sum(float v) {
    #pragma unroll
    for (int off = 16; off > 0; off >>= 1)
        v += __shfl_xor_sync(0xFFFFFFFFu, v, off);
    return v;
}

__global__ __launch_bounds__(NT, 4)   // 64-reg budget, 4 CTAs/SM, one exact wave
void loss_fused_kernel(const float* __restrict__ pred,
                       const float* __restrict__ gt,
                       const float* __restrict__ pred_iou,
                       float*       __restrict__ out) {
    const int tid = threadIdx.x;
    const int img = blockIdx.y;
    const int cta = blockIdx.x;

    // blocked-sequential partition; thread's float8 slot: cta*CHUNK8 + j*NT + tid
    const float* pb = pred + (size_t)img * HW + ((size_t)cta * CHUNK8 + tid) * 8;
    const float* gb = gt   + (size_t)img * HW + ((size_t)cta * CHUNK8 + tid) * 8;

    const int nst = (cta < GRIDX - 1) ? 14 : 8;

    Accs A = {0.f, 0.f, 0.f, 0.f, 0.f, 0.f, 0.f, 0.f};

    // double-buffered 256-bit loads
    f8 p0 = ld256(pb);
    f8 g0 = ld256(gb);
    for (int j = 0; j < nst; j++) {
        f8 p1, g1;
        if (j + 1 < nst) {
            const size_t off = (size_t)(j + 1) * NT * 8;
            p1 = ld256(pb + off);
            g1 = ld256(gb + off);
        }
        octet(A, p0, g0);
        p0 = p1; g0 = g1;
    }

    // -------- block reduction --------
    float vals[NQ] = {A.g, A.tg, A.lg, A.om, A.to, A.t, A.bn, A.bt};
    #pragma unroll
    for (int q = 0; q < NQ; q++) vals[q] = warp_sum(vals[q]);

    __shared__ float sm[NT / 32][NQ];
    const int lane = tid & 31;
    const int warp = tid >> 5;
    if (lane == 0) {
        #pragma unroll
        for (int q = 0; q < NQ; q++) sm[warp][q] = vals[q];
    }
    __syncthreads();

    __shared__ bool is_img_last;
    if (warp == 0) {
        #pragma unroll
        for (int q = 0; q < NQ; q++) {
            float v = (lane < NT / 32) ? sm[lane][q] : 0.0f;
            v = warp_sum(v);
            if (lane == 0) vals[q] = v;
        }
        if (lane == 0) {
            float* dst = g_part + ((size_t)img * GRIDX + cta) * NQ;
            #pragma unroll
            for (int q = 0; q < NQ; q++) dst[q] = vals[q];
            __threadfence();
            unsigned int v = atomicAdd(&g_cnt_img[img], 1u);
            is_img_last = (v == (unsigned int)(GRIDX - 1));
        }
    }
    __syncthreads();
    if (!is_img_last) return;

    // -------- per-image reduction (overlaps other images' streaming) --------
    if (warp == 0) {
        float s[NQ] = {0.f, 0.f, 0.f, 0.f, 0.f, 0.f, 0.f, 0.f};
        for (int j = lane; j < GRIDX; j += 32) {
            const float* q = g_part + ((size_t)img * GRIDX + j) * NQ;
            #pragma unroll
            for (int k = 0; k < NQ; k++) s[k] += q[k];
        }
        #pragma unroll
        for (int k = 0; k < NQ; k++) s[k] = warp_sum(s[k]);

        if (lane == 0) {
            // s: 0=g 1=tg 2=lg 3=om 4=to 5=t 6=bn 7=bt
            float Sp  = s[3] + s[5] - 2.0f * s[4];   // sum p
            float Spt = s[5] - s[4];                 // sum p*t
            float dice_term = (2.0f * Spt + SMOOTH) / (Sp + s[5] + SMOOTH);
            float inter  = s[7];
            float uni    = s[6] + s[5] - s[7];
            float actual = (inter + SMOOTH) / (uni + SMOOTH);
            float d = pred_iou[img] - actual;

            float* gi = g_img + img * 4;
            gi[0] = 0.75f * s[0] - 0.5f * s[1];      // focal partial (x -ln2 later)
            gi[1] = s[2];                            // sum lg2(p_t) (x -ln2 = sum ce)
            gi[2] = dice_term;
            gi[3] = d * d;
            g_cnt_img[img] = 0u;                     // reset for next replay

            __threadfence();
            unsigned int w = atomicAdd(&g_count, 1u);
            if (w == (unsigned int)(BATCH - 1)) {
                // -------- final combine: 16 images x 4 stats --------
                float fsum = 0.f, csum = 0.f, dsum = 0.f, isum = 0.f;
                #pragma unroll
                for (int b = 0; b < BATCH; b++) {
                    const float* q = g_img + b * 4;
                    fsum += q[0];
                    csum += q[1];
                    dsum += q[2];
                    isum += q[3];
                }
                const float NLN2 = -0.6931471805599453f;
                const float invN = 1.0f / (float)((long long)BATCH * HW);
                float focal    = NLN2 * fsum * invN;
                float dice     = 1.0f - dsum / (float)BATCH;
                float boundary = NLN2 * csum * invN;   // mean(ce) = 0.5*(2*mean(ce))
                float iou_loss = 0.1f * (isum / (float)BATCH);
                out[0] = focal + dice + boundary + iou_loss;
                g_count = 0u;                          // reset for next replay
            }
        }
    }
}

extern "C" void kernel_launch(void* const* d_in, const int* in_sizes, int n_in,
                              void* d_out, int out_size) {
    const float* pred = (const float*)d_in[0];
    const float* gt   = (const float*)d_in[1];
    const float* piou = (const float*)d_in[2];
    float* out = (float*)d_out;

    dim3 grid(GRIDX, BATCH);
    loss_fused_kernel<<<grid, NT>>>(pred, gt, piou, out);
}

// round 17
// speedup vs baseline: 1.0088x; 1.0088x over previous
#include <cuda_runtime.h>
#include <cstdint>

// Problem constants
#define BATCH    16
#define HW       (1024 * 1024)
#define HW8      (HW / 8)          // 131072 float8 per image = 512 stages of NT
#define GRIDX    37                // 37*16 = 592 = 148 SMs * 4 CTAs -> one wave
#define NT       256
#define NQ       8                 // g, tg, lg, om, to, t, bn, bt
#define SMOOTH   1e-6f

// Balanced partition of 512 stages over 37 CTAs: 31 CTAs x 14 + 6 CTAs x 13.
// Stage base for cta: 13*cta + min(cta, 31).

__device__ float        g_part[BATCH * GRIDX * NQ];
__device__ float        g_img[BATCH * 4];     // per-image reduced stats
__device__ unsigned int g_cnt_img[BATCH];     // zero-init; self-reset by finisher
__device__ unsigned int g_count;              // zero-init; self-reset by finisher

// ---------- 256-bit streaming load (sm_100+) ----------
struct f8 { float a, b, c, d, e, f, g, h; };
__device__ __forceinline__ f8 ld256(const float* p) {
    f8 r;
    asm volatile("ld.global.nc.v8.f32 {%0,%1,%2,%3,%4,%5,%6,%7}, [%8];"
                 : "=f"(r.a), "=f"(r.b), "=f"(r.c), "=f"(r.d),
                   "=f"(r.e), "=f"(r.f), "=f"(r.g), "=f"(r.h)
                 : "l"(p));
    return r;
}

// ---------- scalar MUFU helpers ----------
__device__ __forceinline__ float tanha(float x) {
    float r; asm("tanh.approx.f32 %0, %1;" : "=f"(r) : "f"(x)); return r;
}
__device__ __forceinline__ float lg2a(float x) {
    float r; asm("lg2.approx.f32 %0, %1;" : "=f"(r) : "f"(x)); return r;
}
__device__ __forceinline__ float setgt0(float x) {
    float r; asm("set.gt.f32.f32 %0, %1, 0f00000000;" : "=f"(r) : "f"(x)); return r;
}

struct Accs { float g, tg, lg, om, to, t, bn, bt; };

// Per-element, t in {0,1}:
//   h = tanh((t-0.5)x) ; p_t = 0.5+0.5h ; l = lg2(p_t)  (ce = -ln2*l)
//   omp = 1-p_t = 0.5-0.5h ; focal elem = (0.75-0.5t)*(-ln2)*l*omp^2
//   Sp = om + t - 2*to ; Spt = t - to     (recovered at image level)
__device__ __forceinline__ void elem(Accs& A, float x, float t) {
    float z   = (t - 0.5f) * x;
    float h   = tanha(z);
    float pt  = fmaf(h, 0.5f, 0.5f);
    float l   = lg2a(pt);
    float omp = fmaf(h, -0.5f, 0.5f);
    float gg  = l * omp * omp;
    A.g  += gg;
    A.tg  = fmaf(t, gg, A.tg);
    A.lg += l;
    A.om += omp;
    A.to  = fmaf(t, omp, A.to);
    A.t  += t;
    float b = setgt0(x);
    A.bn += b;
    A.bt  = fmaf(t, b, A.bt);
}

__device__ __forceinline__ void octet(Accs& A, const f8& p, const f8& g) {
    elem(A, p.a, g.a); elem(A, p.b, g.b);
    elem(A, p.c, g.c); elem(A, p.d, g.d);
    elem(A, p.e, g.e); elem(A, p.f, g.f);
    elem(A, p.g, g.g); elem(A, p.h, g.h);
}

__device__ __forceinline__ float warp_sum(float v) {
    #pragma unroll
    for (int off = 16; off > 0; off >>= 1)
        v += __shfl_xor_sync(0xFFFFFFFFu, v, off);
    return v;
}

__global__ __launch_bounds__(NT, 4)   // 64-reg budget, 4 CTAs/SM, one exact wave
void loss_fused_kernel(const float* __restrict__ pred,
                       const float* __restrict__ gt,
                       const float* __restrict__ pred_iou,
                       float*       __restrict__ out) {
    const int tid = threadIdx.x;
    const int img = blockIdx.y;
    const int cta = blockIdx.x;

    // balanced blocked partition
    const int sbase = 13 * cta + (cta < 31 ? cta : 31);   // first stage index
    const int nst   = (cta < 31) ? 14 : 13;

    const float* pb = pred + (size_t)img * HW + ((size_t)sbase * NT + tid) * 8;
    const float* gb = gt   + (size_t)img * HW + ((size_t)sbase * NT + tid) * 8;

    Accs A = {0.f, 0.f, 0.f, 0.f, 0.f, 0.f, 0.f, 0.f};

    // double-buffered 256-bit loads over contiguous stages
    f8 p0 = ld256(pb);
    f8 g0 = ld256(gb);
    for (int j = 0; j < nst; j++) {
        f8 p1, g1;
        if (j + 1 < nst) {
            const size_t off = (size_t)(j + 1) * NT * 8;
            p1 = ld256(pb + off);
            g1 = ld256(gb + off);
        }
        octet(A, p0, g0);
        p0 = p1; g0 = g1;
    }

    // -------- block reduction --------
    float vals[NQ] = {A.g, A.tg, A.lg, A.om, A.to, A.t, A.bn, A.bt};
    #pragma unroll
    for (int q = 0; q < NQ; q++) vals[q] = warp_sum(vals[q]);

    __shared__ float sm[NT / 32][NQ];
    const int lane = tid & 31;
    const int warp = tid >> 5;
    if (lane == 0) {
        #pragma unroll
        for (int q = 0; q < NQ; q++) sm[warp][q] = vals[q];
    }
    __syncthreads();

    __shared__ bool is_img_last;
    if (warp == 0) {
        #pragma unroll
        for (int q = 0; q < NQ; q++) {
            float v = (lane < NT / 32) ? sm[lane][q] : 0.0f;
            v = warp_sum(v);
            if (lane == 0) vals[q] = v;
        }
        if (lane == 0) {
            float* dst = g_part + ((size_t)img * GRIDX + cta) * NQ;
            #pragma unroll
            for (int q = 0; q < NQ; q++) dst[q] = vals[q];
            __threadfence();
            unsigned int v = atomicAdd(&g_cnt_img[img], 1u);
            is_img_last = (v == (unsigned int)(GRIDX - 1));
        }
    }
    __syncthreads();
    if (!is_img_last) return;

    // -------- per-image reduction (overlaps other images' streaming) --------
    if (warp == 0) {
        float s[NQ] = {0.f, 0.f, 0.f, 0.f, 0.f, 0.f, 0.f, 0.f};
        for (int j = lane; j < GRIDX; j += 32) {
            const float* q = g_part + ((size_t)img * GRIDX + j) * NQ;
            #pragma unroll
            for (int k = 0; k < NQ; k++) s[k] += q[k];
        }
        #pragma unroll
        for (int k = 0; k < NQ; k++) s[k] = warp_sum(s[k]);

        if (lane == 0) {
            // s: 0=g 1=tg 2=lg 3=om 4=to 5=t 6=bn 7=bt
            float Sp  = s[3] + s[5] - 2.0f * s[4];   // sum p
            float Spt = s[5] - s[4];                 // sum p*t
            float dice_term = (2.0f * Spt + SMOOTH) / (Sp + s[5] + SMOOTH);
            float inter  = s[7];
            float uni    = s[6] + s[5] - s[7];
            float actual = (inter + SMOOTH) / (uni + SMOOTH);
            float d = pred_iou[img] - actual;

            float* gi = g_img + img * 4;
            gi[0] = 0.75f * s[0] - 0.5f * s[1];      // focal partial (x -ln2 later)
            gi[1] = s[2];                            // sum lg2(p_t) (x -ln2 = sum ce)
            gi[2] = dice_term;
            gi[3] = d * d;
            g_cnt_img[img] = 0u;                     // reset for next replay

            __threadfence();
            unsigned int w = atomicAdd(&g_count, 1u);
            if (w == (unsigned int)(BATCH - 1)) {
                // -------- final combine: 16 images x 4 stats --------
                float fsum = 0.f, csum = 0.f, dsum = 0.f, isum = 0.f;
                #pragma unroll
                for (int b = 0; b < BATCH; b++) {
                    const float* q = g_img + b * 4;
                    fsum += q[0];
                    csum += q[1];
                    dsum += q[2];
                    isum += q[3];
                }
                const float NLN2 = -0.6931471805599453f;
                const float invN = 1.0f / (float)((long long)BATCH * HW);
                float focal    = NLN2 * fsum * invN;
                float dice     = 1.0f - dsum / (float)BATCH;
                float boundary = NLN2 * csum * invN;   // mean(ce) = 0.5*(2*mean(ce))
                float iou_loss = 0.1f * (isum / (float)BATCH);
                out[0] = focal + dice + boundary + iou_loss;
                g_count = 0u;                          // reset for next replay
            }
        }
    }
}

extern "C" void kernel_launch(void* const* d_in, const int* in_sizes, int n_in,
                              void* d_out, int out_size) {
    const float* pred = (const float*)d_in[0];
    const float* gt   = (const float*)d_in[1];
    const float* piou = (const float*)d_in[2];
    float* out = (float*)d_out;

    dim3 grid(GRIDX, BATCH);
    loss_fused_kernel<<<grid, NT>>>(pred, gt, piou, out);
}